// round 2
// baseline (speedup 1.0000x reference)
#include <cuda_runtime.h>

#define Tlen 1000
#define Bsz  4096
#define INsz 8
#define Hsz  50
#define Osz  6
#define NDIM 56        // 50 h dims + 6 y dims
#define WROW 60        // weight row: [0..49]=W_rec/W_out, [50,51]=0, [52..59]=W_in/0
#define VROW 68        // v row stride in floats (17 x 16B -> conflict-free)
#define BTILE 32

__device__ __forceinline__ void fma2(unsigned long long& acc,
                                     unsigned long long a,
                                     unsigned long long b) {
    asm("fma.rn.f32x2 %0, %1, %2, %0;" : "+l"(acc) : "l"(a), "l"(b));
}

__device__ __forceinline__ float hadd2(unsigned long long a) {
    float lo, hi;
    asm("mov.b64 {%0, %1}, %2;" : "=f"(lo), "=f"(hi) : "l"(a));
    return lo + hi;
}

__global__ void __launch_bounds__(256, 1) biornn_kernel(
    const float* __restrict__ x,       // (T, B, 8)
    const float* __restrict__ W_in,    // (50, 8)
    const float* __restrict__ W_rec,   // (50, 50)
    const float* __restrict__ bias,    // (50,)
    const float* __restrict__ W_out_w, // (6, 50)
    const float* __restrict__ W_out_b, // (6,)
    float* __restrict__ out)           // (T, B, 6)
{
    __shared__ __align__(16) float sW[NDIM * WROW];
    __shared__ __align__(16) float sV[2 * BTILE * VROW];
    __shared__ float sB[NDIM];

    const int tid = threadIdx.x;

    // ---- stage weights (concatenated + padded) into shared ----
    for (int i = tid; i < NDIM * WROW; i += 256) {
        int d = i / WROW, j = i - d * WROW;
        float w = 0.f;
        if (d < Hsz) {
            if (j < Hsz)       w = W_rec[d * Hsz + j];
            else if (j >= 52)  w = W_in[d * INsz + (j - 52)];
        } else {
            if (j < Hsz)       w = W_out_w[(d - Hsz) * Hsz + j];
        }
        sW[i] = w;
    }
    // zero v buffers once (pads j=50,51 must stay 0 forever)
    for (int i = tid; i < 2 * BTILE * VROW; i += 256) sV[i] = 0.f;
    for (int i = tid; i < NDIM; i += 256)
        sB[i] = (i < Hsz) ? bias[i] : W_out_b[i - Hsz];
    __syncthreads();

    const int b = tid & 31;    // batch within tile (warp-lane)
    const int g = tid >> 5;    // dim group (warp id), 7 dims each
    const int gb0 = blockIdx.x * BTILE;   // global batch base

    float h[7], br[7];
    #pragma unroll
    for (int dl = 0; dl < 7; dl++) {
        h[dl]  = 0.f;
        br[dl] = sB[g * 7 + dl];
    }

    const float* wbase = sW + g * 7 * WROW;

    // ---- prefetch x for t = 0 into registers (warp 0 owns x) ----
    float4 x0, x1;
    if (g == 0) {
        const float4* xp = reinterpret_cast<const float4*>(x);
        size_t base = ((size_t)0 * Bsz + gb0 + b) * 2;   // 2 float4 per batch elem
        x0 = xp[base + 0];
        x1 = xp[base + 1];
    }

    #pragma unroll 1
    for (int t = 0; t < Tlen; t++) {
        float* vr = sV + (t & 1) * (BTILE * VROW) + b * VROW;

        // ---- publish r = relu(h) for owned h dims ----
        if (g < 7) {
            #pragma unroll
            for (int dl = 0; dl < 7; dl++)
                vr[g * 7 + dl] = fmaxf(h[dl], 0.f);
        } else {
            vr[49] = fmaxf(h[0], 0.f);
        }

        // ---- publish x_t (from regs), prefetch x_{t+1} ----
        if (g == 0) {
            *reinterpret_cast<float4*>(vr + 52) = x0;
            *reinterpret_cast<float4*>(vr + 56) = x1;
            if (t + 1 < Tlen) {
                const float4* xp = reinterpret_cast<const float4*>(x);
                size_t base = ((size_t)(t + 1) * Bsz + gb0 + b) * 2;
                x0 = xp[base + 0];
                x1 = xp[base + 1];
            }
        }
        __syncthreads();   // single barrier per step (double-buffered v)

        // ---- fused matvec: 7 dims x 1 batch, f32x2 packed along j ----
        unsigned long long acc[7];
        #pragma unroll
        for (int dl = 0; dl < 7; dl++) acc[dl] = 0ull;

        const ulonglong2* va = reinterpret_cast<const ulonglong2*>(vr);
        #pragma unroll
        for (int jb = 0; jb < 15; jb++) {
            ulonglong2 a = va[jb];
            #pragma unroll
            for (int dl = 0; dl < 7; dl++) {
                ulonglong2 w =
                    reinterpret_cast<const ulonglong2*>(wbase + dl * WROW)[jb];
                fma2(acc[dl], a.x, w.x);
                fma2(acc[dl], a.y, w.y);
            }
        }

        // ---- finalize: h update (dims < 50) / y output (dims 50..55) ----
        if (g < 7) {
            #pragma unroll
            for (int dl = 0; dl < 7; dl++) {
                float s = hadd2(acc[dl]) + br[dl];
                h[dl] = fmaf(0.1f, s - h[dl], h[dl]);
            }
        } else {
            {   // dim 49 is an h dim
                float s = hadd2(acc[0]) + br[0];
                h[0] = fmaf(0.1f, s - h[0], h[0]);
            }
            size_t ob = ((size_t)t * Bsz + gb0 + b) * Osz;
            #pragma unroll
            for (int dl = 1; dl < 7; dl++)
                out[ob + (dl - 1)] = hadd2(acc[dl]) + br[dl];
        }
    }
}

extern "C" void kernel_launch(void* const* d_in, const int* in_sizes, int n_in,
                              void* d_out, int out_size) {
    const float* x        = (const float*)d_in[0];
    const float* W_in     = (const float*)d_in[1];
    const float* W_rec    = (const float*)d_in[2];
    const float* bias     = (const float*)d_in[3];
    const float* W_out_w  = (const float*)d_in[4];
    const float* W_out_b  = (const float*)d_in[5];
    float* out = (float*)d_out;

    biornn_kernel<<<Bsz / BTILE, 256>>>(x, W_in, W_rec, bias,
                                        W_out_w, W_out_b, out);
}

// round 3
// speedup vs baseline: 2.1602x; 2.1602x over previous
#include <cuda_runtime.h>

#define Tlen 1000
#define Bsz  4096
#define INsz 8
#define Hsz  50
#define Osz  6
#define NDIM 56        // 50 h dims + 6 y dims
// Row layout (68 words): words[0..31]   = j 0..31   (half 0)
//                        words[32..35]  = pad (zero)
//                        words[36..67]  = j 32..63  (half 1)
// j semantics: j<50 -> W_rec/W_out | v=relu(h);  50..55 -> zero pad;
//              56..63 -> W_in | v=x_t
#define ROWW 68
#define BTILE 32

__device__ __forceinline__ void fma2(unsigned long long& acc,
                                     unsigned long long a,
                                     unsigned long long b) {
    asm("fma.rn.f32x2 %0, %1, %2, %0;" : "+l"(acc) : "l"(a), "l"(b));
}

__device__ __forceinline__ float hadd2(unsigned long long a) {
    float lo, hi;
    asm("mov.b64 {%0, %1}, %2;" : "=f"(lo), "=f"(hi) : "l"(a));
    return lo + hi;
}

__global__ void __launch_bounds__(256, 1) biornn_kernel(
    const float* __restrict__ x,       // (T, B, 8)
    const float* __restrict__ W_in,    // (50, 8)
    const float* __restrict__ W_rec,   // (50, 50)
    const float* __restrict__ bias,    // (50,)
    const float* __restrict__ W_out_w, // (6, 50)
    const float* __restrict__ W_out_b, // (6,)
    float* __restrict__ out)           // (T, B, 6)
{
    __shared__ __align__(16) float sW[NDIM * ROWW];
    __shared__ __align__(16) float sV[2 * BTILE * ROWW];
    __shared__ float sB[NDIM];

    const int tid = threadIdx.x;

    // ---- stage weights into padded/split rows ----
    for (int i = tid; i < NDIM * ROWW; i += 256) {
        int d = i / ROWW, w = i - d * ROWW;
        float val = 0.f;
        if (w < 32 || w >= 36) {
            int j = (w < 32) ? w : (w - 4);
            if (d < Hsz) {
                if (j < Hsz)       val = W_rec[d * Hsz + j];
                else if (j >= 56)  val = W_in[d * INsz + (j - 56)];
            } else {
                if (j < Hsz)       val = W_out_w[(d - Hsz) * Hsz + j];
            }
        }
        sW[i] = val;
    }
    for (int i = tid; i < 2 * BTILE * ROWW; i += 256) sV[i] = 0.f;
    for (int i = tid; i < NDIM; i += 256)
        sB[i] = (i < Hsz) ? bias[i] : W_out_b[i - Hsz];
    __syncthreads();

    const int lane = tid & 31;
    const int g    = tid >> 5;          // dim-group (warp), 7 dims each
    const int p    = lane & 15;         // batch-pair slot
    const int half = lane >> 4;         // j-half
    const int rowp = p + 16 * half;     // batch this lane "owns" (publish/x/out)
    const int gb0  = blockIdx.x * BTILE;

    // h for the owned batch only; bias; publish word indices
    float h[7], br[7];
    int wd[7];
    #pragma unroll
    for (int dl = 0; dl < 7; dl++) {
        h[dl]  = 0.f;
        br[dl] = sB[g * 7 + dl];
        int jj = g * 7 + dl;
        wd[dl] = (jj < 32) ? jj : jj + 4;
    }

    // ---- prefetch x for t = 0 (warp 0; lane covers batch rowp) ----
    float4 x0, x1;
    if (g == 0) {
        const float4* xp = reinterpret_cast<const float4*>(x);
        size_t base = ((size_t)0 * Bsz + gb0 + rowp) * 2;
        x0 = xp[base + 0];
        x1 = xp[base + 1];
    }

    #pragma unroll 1
    for (int t = 0; t < Tlen; t++) {
        float* vb  = sV + (t & 1) * (BTILE * ROWW);
        float* own = vb + rowp * ROWW;

        // ---- publish r = relu(h) for owned batch's dims ----
        if (g < 7) {
            #pragma unroll
            for (int dl = 0; dl < 7; dl++)
                own[wd[dl]] = fmaxf(h[dl], 0.f);
        } else {
            own[wd[0]] = fmaxf(h[0], 0.f);   // dim 49
        }

        // ---- publish x_t, prefetch x_{t+1} (warp 0) ----
        if (g == 0) {
            *reinterpret_cast<float4*>(own + 60) = x0;
            *reinterpret_cast<float4*>(own + 64) = x1;
            if (t + 1 < Tlen) {
                const float4* xp = reinterpret_cast<const float4*>(x);
                size_t base = ((size_t)(t + 1) * Bsz + gb0 + rowp) * 2;
                x0 = xp[base + 0];
                x1 = xp[base + 1];
            }
        }
        __syncthreads();   // single barrier per step (double-buffered v)

        // ---- half-matvec: 7 dims x 2 batches, this lane's 32-float j-half ----
        unsigned long long acc0[7], acc1[7];
        #pragma unroll
        for (int dl = 0; dl < 7; dl++) { acc0[dl] = 0ull; acc1[dl] = 0ull; }

        const ulonglong2* va =
            reinterpret_cast<const ulonglong2*>(vb + p * ROWW + half * 36);
        const ulonglong2* vc =
            reinterpret_cast<const ulonglong2*>(vb + (p + 16) * ROWW + half * 36);
        const float* wb = sW + g * 7 * ROWW + half * 36;

        #pragma unroll
        for (int jb = 0; jb < 8; jb++) {
            ulonglong2 a = va[jb];
            ulonglong2 c = vc[jb];
            #pragma unroll
            for (int dl = 0; dl < 7; dl++) {
                ulonglong2 w =
                    reinterpret_cast<const ulonglong2*>(wb + dl * ROWW)[jb];
                fma2(acc0[dl], a.x, w.x);
                fma2(acc0[dl], a.y, w.y);
                fma2(acc1[dl], c.x, w.x);
                fma2(acc1[dl], c.y, w.y);
            }
        }

        // ---- combine halves (shfl xor 16), finalize own batch ----
        size_t obase = ((size_t)t * Bsz + gb0 + rowp) * Osz;
        #pragma unroll
        for (int dl = 0; dl < 7; dl++) {
            float a0 = hadd2(acc0[dl]);
            float a1 = hadd2(acc1[dl]);
            a0 += __shfl_xor_sync(0xffffffffu, a0, 16);
            a1 += __shfl_xor_sync(0xffffffffu, a1, 16);
            float so = (half ? a1 : a0) + br[dl];
            if (g < 7 || dl == 0) {
                h[dl] = fmaf(0.1f, so - h[dl], h[dl]);   // h update
            } else {
                out[obase + (dl - 1)] = so;              // y output
            }
        }
    }
}

extern "C" void kernel_launch(void* const* d_in, const int* in_sizes, int n_in,
                              void* d_out, int out_size) {
    const float* x        = (const float*)d_in[0];
    const float* W_in     = (const float*)d_in[1];
    const float* W_rec    = (const float*)d_in[2];
    const float* bias     = (const float*)d_in[3];
    const float* W_out_w  = (const float*)d_in[4];
    const float* W_out_b  = (const float*)d_in[5];
    float* out = (float*)d_out;

    biornn_kernel<<<Bsz / BTILE, 256>>>(x, W_in, W_rec, bias,
                                        W_out_w, W_out_b, out);
}